// round 14
// baseline (speedup 1.0000x reference)
#include <cuda_runtime.h>
#include <cstdint>
#include <cstddef>

// ---------------------------------------------------------------------------
// SpatialBottleneck: conv1x1(256->64)+sb+relu -> conv3x3(64->64,pad1)+sb+relu
//                    -> conv1x1(64->256)+sb + residual(x) + relu
// N=16, H=W=128, fp32 in/out. Compute in TF32 via mma.sync (m16n8k8),
// round-to-nearest conversion on all operands. Intermediates live in
// __device__ scratch (67 MB each -> L2-resident on GB300's 126 MB L2).
// ---------------------------------------------------------------------------

namespace {
constexpr int BATCH = 16;
constexpr int CIN   = 256;
constexpr int CB    = 64;
constexpr int COUT  = 256;
constexpr int H     = 128;
constexpr int W     = 128;
constexpr int P     = H * W;       // 16384 pixels per (n, c) plane
}

__device__ float g_out1[(size_t)BATCH * CB * P];   // 67 MB scratch
__device__ float g_out2[(size_t)BATCH * CB * P];   // 67 MB scratch

__device__ __forceinline__ uint32_t f2tf(float f) {
    uint32_t u;
    asm("cvt.rna.tf32.f32 %0, %1;" : "=r"(u) : "f"(f));
    return u;
}

// D = A(16x8) * B(8x8) + D, tf32 inputs, f32 accum.
// Fragment layout (PTX ISA, m16n8k8.tf32): grp=lane>>2, tig=lane&3
//   a0:(grp,tig) a1:(grp+8,tig) a2:(grp,tig+4) a3:(grp+8,tig+4)
//   b0:(k=tig,n=grp) b1:(k=tig+4,n=grp)
//   c0:(grp,2*tig) c1:(grp,2*tig+1) c2:(grp+8,2*tig) c3:(grp+8,2*tig+1)
__device__ __forceinline__ void mma_tf32(float* c, const uint32_t* a,
                                         uint32_t b0, uint32_t b1) {
    asm("mma.sync.aligned.m16n8k8.row.col.f32.tf32.tf32.f32 "
        "{%0,%1,%2,%3}, {%4,%5,%6,%7}, {%8,%9}, {%0,%1,%2,%3};"
        : "+f"(c[0]), "+f"(c[1]), "+f"(c[2]), "+f"(c[3])
        : "r"(a[0]), "r"(a[1]), "r"(a[2]), "r"(a[3]), "r"(b0), "r"(b1));
}

namespace { constexpr int BSTR = 264; }  // 256 pixels padded (≡8 mod 32)

// ===========================================================================
// Kernel 1: out1[n,c,p] = relu( sum_k (w1[c,k]*s1[c]) * x[n,k,p] + b1[c] )
// GEMM: M=64 (all out channels), N=256 pixels/block, K=256 (tiled by 32).
// 8 warps as 2(M) x 4(N); warp tile 32x64; per warp 2x8 mma tiles.
// Register-prefetch pipeline: tile t+1's LDGs (DRAM) issue before tile t's
// compute phase, hiding DRAM latency under the 512-MMA compute block.
// ===========================================================================
__global__ __launch_bounds__(256, 2) void conv1x1_k1(
    const float* __restrict__ x, const float* __restrict__ w1,
    const float* __restrict__ s1, const float* __restrict__ b1)
{
    __shared__ __align__(16) uint32_t As[64 * 36];     // 9.2 KB [c][k]
    __shared__ __align__(16) uint32_t Bs[32 * BSTR];   // 33.8 KB [k][p]

    const int n     = blockIdx.y;
    const int pBase = blockIdx.x * 256;
    const int tid   = threadIdx.x;
    const int lane  = tid & 31;
    const int warp  = tid >> 5;
    const int wM = warp & 1, wN = warp >> 1;
    const int grp = lane >> 2, tig = lane & 3;

    float acc[2][8][4];
    #pragma unroll
    for (int mt = 0; mt < 2; mt++)
        #pragma unroll
        for (int nt = 0; nt < 8; nt++)
            #pragma unroll
            for (int j = 0; j < 4; j++) acc[mt][nt][j] = 0.f;

    // Per-thread staging slices (fixed across tiles):
    //   A: 8 elements, i = tid + u*256 -> c = i>>5, k = i&31
    //   B: 8 float4s,  i = tid + u*256 -> k = i>>6, p4 = i&63
    float  aReg[8];
    float4 bReg[8];

    // Prologue: prefetch tile 0
    #pragma unroll
    for (int u = 0; u < 8; u++) {
        int i = tid + u * 256;
        int c = i >> 5, k = i & 31;
        aReg[u] = w1[c * CIN + k] * s1[c];
    }
    #pragma unroll
    for (int u = 0; u < 8; u++) {
        int i = tid + u * 256;
        int k = i >> 6, p4 = i & 63;
        bReg[u] = *reinterpret_cast<const float4*>(
            x + ((size_t)(n * CIN + k) << 14) + pBase + p4 * 4);
    }

    for (int t = 0; t < CIN / 32; t++) {
        __syncthreads();   // previous compute done -> safe to overwrite smem
        // Commit prefetched tile t to smem (cvt on the way in)
        #pragma unroll
        for (int u = 0; u < 8; u++) {
            int i = tid + u * 256;
            int c = i >> 5, k = i & 31;
            As[c * 36 + k] = f2tf(aReg[u]);
        }
        #pragma unroll
        for (int u = 0; u < 8; u++) {
            int i = tid + u * 256;
            int k = i >> 6, p4 = i & 63;
            uint4 tv;
            tv.x = f2tf(bReg[u].x); tv.y = f2tf(bReg[u].y);
            tv.z = f2tf(bReg[u].z); tv.w = f2tf(bReg[u].w);
            *reinterpret_cast<uint4*>(&Bs[k * BSTR + p4 * 4]) = tv;
        }
        __syncthreads();

        // Issue prefetch LDGs for tile t+1 (in flight during compute below)
        if (t + 1 < CIN / 32) {
            const int kt = (t + 1) * 32;
            #pragma unroll
            for (int u = 0; u < 8; u++) {
                int i = tid + u * 256;
                int c = i >> 5, k = i & 31;
                aReg[u] = w1[c * CIN + kt + k] * s1[c];
            }
            #pragma unroll
            for (int u = 0; u < 8; u++) {
                int i = tid + u * 256;
                int k = i >> 6, p4 = i & 63;
                bReg[u] = *reinterpret_cast<const float4*>(
                    x + ((size_t)(n * CIN + kt + k) << 14) + pBase + p4 * 4);
            }
        }

        // Compute tile t
        #pragma unroll
        for (int kk = 0; kk < 32; kk += 8) {
            uint32_t a[2][4];
            #pragma unroll
            for (int mt = 0; mt < 2; mt++) {
                int r = wM * 32 + mt * 16 + grp;
                a[mt][0] = As[r * 36 + kk + tig];
                a[mt][1] = As[(r + 8) * 36 + kk + tig];
                a[mt][2] = As[r * 36 + kk + tig + 4];
                a[mt][3] = As[(r + 8) * 36 + kk + tig + 4];
            }
            #pragma unroll
            for (int nt = 0; nt < 8; nt++) {
                int col = wN * 64 + nt * 8 + grp;
                uint32_t b0  = Bs[(kk + tig) * BSTR + col];
                uint32_t b1v = Bs[(kk + tig + 4) * BSTR + col];
                mma_tf32(acc[0][nt], a[0], b0, b1v);
                mma_tf32(acc[1][nt], a[1], b0, b1v);
            }
        }
    }
    // Epilogue: +bias, relu, store
    #pragma unroll
    for (int mt = 0; mt < 2; mt++) {
        int c = wM * 32 + mt * 16 + grp;
        float bia0 = b1[c], bia1 = b1[c + 8];
        size_t base0 = ((size_t)(n * CB + c) << 14);
        size_t base1 = ((size_t)(n * CB + c + 8) << 14);
        #pragma unroll
        for (int nt = 0; nt < 8; nt++) {
            int pc = pBase + wN * 64 + nt * 8 + tig * 2;
            g_out1[base0 + pc]     = fmaxf(acc[mt][nt][0] + bia0, 0.f);
            g_out1[base0 + pc + 1] = fmaxf(acc[mt][nt][1] + bia0, 0.f);
            g_out1[base1 + pc]     = fmaxf(acc[mt][nt][2] + bia1, 0.f);
            g_out1[base1 + pc + 1] = fmaxf(acc[mt][nt][3] + bia1, 0.f);
        }
    }
}

// ===========================================================================
// Kernel 2: conv3x3 (pad 1), 64->64, + s2/b2 + relu.
// Implicit GEMM over a 16x16 spatial tile (N=256 pixels), M=64 out channels,
// K = 64 ic x 9 taps. IC chunked by 8; per chunk, input tile + halo
// (18x18, zero-filled OOB) AND all 9 taps' weights are staged with TWO
// barriers total, then all 9 taps run back-to-back with zero barriers.
// 8 warps as 2(M) x 4(N); warp tile 32x64; per warp 2x8 mma tiles.
// ===========================================================================
namespace {
constexpr int INS = 328;   // 18*18=324 padded to 328 (stride ≡ 8 mod 32)
constexpr int WST = 76;    // 9 taps * 8 ic = 72 padded to 76 (≡ 12 mod 32:
                           // grp*12+tig mod 32 -> 32 distinct banks)
}

__global__ __launch_bounds__(256) void conv3x3_k2(
    const float* __restrict__ w2, const float* __restrict__ s2,
    const float* __restrict__ b2)
{
    __shared__ __align__(16) uint32_t in_s[8 * INS];    // 10.3 KB
    __shared__ __align__(16) uint32_t w_s[64 * WST];    // 19.0 KB [oc][tap*8+ic]

    const int n  = blockIdx.z;
    const int ty = blockIdx.y * 16;
    const int tx = blockIdx.x * 16;
    const int tid  = threadIdx.x;
    const int lane = tid & 31;
    const int warp = tid >> 5;
    const int wM = warp & 1, wN = warp >> 1;
    const int grp = lane >> 2, tig = lane & 3;

    float acc[2][8][4];
    #pragma unroll
    for (int mt = 0; mt < 2; mt++)
        #pragma unroll
        for (int nt = 0; nt < 8; nt++)
            #pragma unroll
            for (int j = 0; j < 4; j++) acc[mt][nt][j] = 0.f;

    // Pixel->smem offsets for this warp's 8 N-tiles (tap-independent part)
    int prow[8], pcol[8];
    #pragma unroll
    for (int nt = 0; nt < 8; nt++) {
        int p = wN * 64 + nt * 8 + grp;
        prow[nt] = p >> 4;
        pcol[nt] = p & 15;
    }

    for (int icc = 0; icc < 64; icc += 8) {
        __syncthreads();   // protect smem reads of previous chunk
        // Stage input chunk (8 ic) with halo, zero OOB: 8*324 = 2592 words
        for (int i = tid; i < 8 * 324; i += 256) {
            int ic = i / 324;
            int r  = i - ic * 324;
            int yy = r / 18;
            int xx = r - yy * 18;
            int gy = ty + yy - 1, gx = tx + xx - 1;
            float v = 0.f;
            if ((unsigned)gy < (unsigned)H && (unsigned)gx < (unsigned)W)
                v = g_out1[((size_t)(n * CB + icc + ic) << 14) + gy * W + gx];
            in_s[ic * INS + yy * 18 + xx] = f2tf(v);
        }
        // Stage ALL 9 taps' weights for this chunk, fold s2: 64*72 = 4608 words
        for (int i = tid; i < 64 * 72; i += 256) {
            int oc  = i / 72;
            int rem = i - oc * 72;
            int tap = rem >> 3;
            int ic  = rem & 7;
            w_s[oc * WST + tap * 8 + ic] =
                f2tf(w2[(oc * 64 + icc + ic) * 9 + tap] * s2[oc]);
        }
        __syncthreads();

        #pragma unroll
        for (int tap = 0; tap < 9; tap++) {
            const int dy = tap / 3, dx = tap - dy * 3;
            uint32_t a[2][4];
            #pragma unroll
            for (int mt = 0; mt < 2; mt++) {
                int r = wM * 32 + mt * 16 + grp;
                a[mt][0] = w_s[r * WST + tap * 8 + tig];
                a[mt][1] = w_s[(r + 8) * WST + tap * 8 + tig];
                a[mt][2] = w_s[r * WST + tap * 8 + tig + 4];
                a[mt][3] = w_s[(r + 8) * WST + tap * 8 + tig + 4];
            }
            #pragma unroll
            for (int nt = 0; nt < 8; nt++) {
                int boff = (prow[nt] + dy) * 18 + pcol[nt] + dx;
                uint32_t b0  = in_s[tig * INS + boff];
                uint32_t b1v = in_s[(tig + 4) * INS + boff];
                mma_tf32(acc[0][nt], a[0], b0, b1v);
                mma_tf32(acc[1][nt], a[1], b0, b1v);
            }
        }
    }
    // Epilogue: +bias, relu, store
    #pragma unroll
    for (int mt = 0; mt < 2; mt++) {
        int c = wM * 32 + mt * 16 + grp;
        float bia0 = b2[c], bia1 = b2[c + 8];
        size_t base0 = ((size_t)(n * CB + c) << 14);
        size_t base1 = ((size_t)(n * CB + c + 8) << 14);
        #pragma unroll
        for (int nt = 0; nt < 8; nt++) {
            int p  = wN * 64 + nt * 8 + tig * 2;
            int gp = (ty + (p >> 4)) * W + tx + (p & 15);
            g_out2[base0 + gp]     = fmaxf(acc[mt][nt][0] + bia0, 0.f);
            g_out2[base0 + gp + 1] = fmaxf(acc[mt][nt][1] + bia0, 0.f);
            g_out2[base1 + gp]     = fmaxf(acc[mt][nt][2] + bia1, 0.f);
            g_out2[base1 + gp + 1] = fmaxf(acc[mt][nt][3] + bia1, 0.f);
        }
    }
}

// ===========================================================================
// Kernel 3: out[n,c,p] = relu( sum_k (w3[c,k]*s3[c]) * out2[n,k,p]
//                              + b3[c] + x[n,c,p] )
// GEMM: M=64 channels/block (4 M-tiles cover 256), N=256 pixels, K=64.
// 8 warps as 2(M) x 4(N); warp tile 32x64; per warp 2x8 mma tiles.
// ===========================================================================
__global__ __launch_bounds__(256) void conv1x1_k3(
    const float* __restrict__ x, const float* __restrict__ w3,
    const float* __restrict__ s3, const float* __restrict__ b3,
    float* __restrict__ out)
{
    __shared__ __align__(16) uint32_t As[64 * 36];
    __shared__ __align__(16) uint32_t Bs[32 * BSTR];

    const int n     = blockIdx.z;
    const int mBase = blockIdx.y * 64;
    const int pBase = blockIdx.x * 256;
    const int tid   = threadIdx.x;
    const int lane  = tid & 31;
    const int warp  = tid >> 5;
    const int wM = warp & 1, wN = warp >> 1;
    const int grp = lane >> 2, tig = lane & 3;

    float acc[2][8][4];
    #pragma unroll
    for (int mt = 0; mt < 2; mt++)
        #pragma unroll
        for (int nt = 0; nt < 8; nt++)
            #pragma unroll
            for (int j = 0; j < 4; j++) acc[mt][nt][j] = 0.f;

    for (int kt = 0; kt < CB; kt += 32) {
        __syncthreads();
        #pragma unroll
        for (int i = tid; i < 64 * 32; i += 256) {
            int c = i >> 5, k = i & 31;
            int cg = mBase + c;
            As[c * 36 + k] = f2tf(w3[cg * CB + kt + k] * s3[cg]);
        }
        #pragma unroll
        for (int i = tid; i < 32 * 64; i += 256) {
            int k = i >> 6, p4 = i & 63;
            const float4 v = *reinterpret_cast<const float4*>(
                g_out2 + ((size_t)(n * CB + kt + k) << 14) + pBase + p4 * 4);
            uint4 t;
            t.x = f2tf(v.x); t.y = f2tf(v.y); t.z = f2tf(v.z); t.w = f2tf(v.w);
            *reinterpret_cast<uint4*>(&Bs[k * BSTR + p4 * 4]) = t;
        }
        __syncthreads();
        #pragma unroll
        for (int kk = 0; kk < 32; kk += 8) {
            uint32_t a[2][4];
            #pragma unroll
            for (int mt = 0; mt < 2; mt++) {
                int r = wM * 32 + mt * 16 + grp;
                a[mt][0] = As[r * 36 + kk + tig];
                a[mt][1] = As[(r + 8) * 36 + kk + tig];
                a[mt][2] = As[r * 36 + kk + tig + 4];
                a[mt][3] = As[(r + 8) * 36 + kk + tig + 4];
            }
            #pragma unroll
            for (int nt = 0; nt < 8; nt++) {
                int col = wN * 64 + nt * 8 + grp;
                uint32_t b0  = Bs[(kk + tig) * BSTR + col];
                uint32_t b1v = Bs[(kk + tig + 4) * BSTR + col];
                mma_tf32(acc[0][nt], a[0], b0, b1v);
                mma_tf32(acc[1][nt], a[1], b0, b1v);
            }
        }
    }
    // Epilogue: +bias, +residual (vectorized), relu, store
    #pragma unroll
    for (int mt = 0; mt < 2; mt++) {
        int cg = mBase + wM * 32 + mt * 16 + grp;
        float bia0 = b3[cg], bia1 = b3[cg + 8];
        size_t base0 = ((size_t)(n * COUT + cg) << 14);
        size_t base1 = ((size_t)(n * COUT + cg + 8) << 14);
        #pragma unroll
        for (int nt = 0; nt < 8; nt++) {
            int pc = pBase + wN * 64 + nt * 8 + tig * 2;
            const float2 r0 = *reinterpret_cast<const float2*>(x + base0 + pc);
            const float2 r1 = *reinterpret_cast<const float2*>(x + base1 + pc);
            float2 o0, o1;
            o0.x = fmaxf(acc[mt][nt][0] + bia0 + r0.x, 0.f);
            o0.y = fmaxf(acc[mt][nt][1] + bia0 + r0.y, 0.f);
            o1.x = fmaxf(acc[mt][nt][2] + bia1 + r1.x, 0.f);
            o1.y = fmaxf(acc[mt][nt][3] + bia1 + r1.y, 0.f);
            *reinterpret_cast<float2*>(out + base0 + pc) = o0;
            *reinterpret_cast<float2*>(out + base1 + pc) = o1;
        }
    }
}

// ===========================================================================
extern "C" void kernel_launch(void* const* d_in, const int* in_sizes, int n_in,
                              void* d_out, int out_size) {
    const float* x  = (const float*)d_in[0];
    const float* w1 = (const float*)d_in[1];
    const float* w2 = (const float*)d_in[2];
    const float* w3 = (const float*)d_in[3];
    const float* s1 = (const float*)d_in[4];
    const float* b1 = (const float*)d_in[5];
    const float* s2 = (const float*)d_in[6];
    const float* b2 = (const float*)d_in[7];
    const float* s3 = (const float*)d_in[8];
    const float* b3 = (const float*)d_in[9];
    float* out = (float*)d_out;

    conv1x1_k1<<<dim3(P / 256, BATCH), 256>>>(x, w1, s1, b1);
    conv3x3_k2<<<dim3(W / 16, H / 16, BATCH), 256>>>(w2, s2, b2);
    conv1x1_k3<<<dim3(P / 256, COUT / 64, BATCH), 256>>>(x, w3, s3, b3, out);
}